// round 1
// baseline (speedup 1.0000x reference)
#include <cuda_runtime.h>

// Problem constants
#define NROWS 4096
#define AADDR 32768
#define FD    160
#define CDIM  10

// Tiling
#define BM 128
#define BN 64
#define SLICES 8
#define APS (AADDR / SLICES)   // 4096 addresses per slice
#define NCHUNK (APS / BN)      // 64 chunks per block
#define THREADS 256

// SMEM strides (floats), padded for bank-conflict-free access + 16B alignment
#define SA 132   // As[k][m], m stride
#define SB 68    // Bs[k][n]
#define SP 68    // P[m][n]
#define SMST 68  // Mst[c][n]

#define SHIFT_C 16.0f
#define INVB (1.0f / 1.1f)

#define SMEM_FLOATS (FD*SA + 2*FD*SB + BM*SP + 2*CDIM*SMST + 2*BN + BM)
#define SMEM_BYTES (SMEM_FLOATS * 4)

// Scratch (no allocations allowed)
__device__ float g_y2[AADDR];
__device__ float g_partial[SLICES * NROWS * 12];

// ---- packed f32x2 helpers (Blackwell FFMA2) ----
__device__ __forceinline__ unsigned long long dup2(float v) {
    unsigned long long r;
    asm("mov.b64 %0, {%1, %1};" : "=l"(r) : "f"(v));
    return r;
}
__device__ __forceinline__ void fma2(unsigned long long &d,
                                     unsigned long long a,
                                     unsigned long long b) {
    asm("fma.rn.f32x2 %0, %1, %2, %0;" : "+l"(d) : "l"(a), "l"(b));
}
__device__ __forceinline__ float2 unpk(unsigned long long v) {
    float2 r;
    asm("mov.b64 {%0, %1}, %2;" : "=f"(r.x), "=f"(r.y) : "l"(v));
    return r;
}

// ---- prep: y2[a] = ||Address[a]||^2 (also warms L2 with Address) ----
__global__ void prep_y2_kernel(const float* __restrict__ Ad) {
    int row = blockIdx.x * 8 + (threadIdx.x >> 5);
    int lane = threadIdx.x & 31;
    const float* r = Ad + (long long)row * FD;
    float s = 0.f;
    for (int k = lane; k < FD; k += 32) {
        float v = r[k];
        s = fmaf(v, v, s);
    }
    #pragma unroll
    for (int o = 16; o; o >>= 1) s += __shfl_xor_sync(0xffffffffu, s, o);
    if (lane == 0) g_y2[row] = s;
}

// ---- per-chunk loader: Address chunk (transposed K-major), M chunk (transposed), y2 ----
__device__ __forceinline__ void loadChunk(int buf, int aBase,
                                          const float* __restrict__ Ad,
                                          const float* __restrict__ M,
                                          float* Bs, float* Mst, float* y2s,
                                          int t) {
    // B tile: 64 rows x 160 floats -> Bs[k][n]. r = t&63 gives conflict-free STS.
    {
        int r = t & 63;
        int kb = (t >> 6) * 40;
        const float* src = Ad + (long long)(aBase + r) * FD + kb;
        float* B = Bs + buf * (FD * SB);
        #pragma unroll
        for (int i = 0; i < 40; i += 4) {
            float4 v = *(const float4*)(src + i);
            B[(kb + i + 0) * SB + r] = v.x;
            B[(kb + i + 1) * SB + r] = v.y;
            B[(kb + i + 2) * SB + r] = v.z;
            B[(kb + i + 3) * SB + r] = v.w;
        }
    }
    // M chunk transposed: Mst[c][n]
    {
        float* Mb = Mst + buf * (CDIM * SMST);
        for (int idx = t; idx < BN * CDIM; idx += THREADS) {
            int n = idx / CDIM;
            int c = idx - n * CDIM;
            Mb[c * SMST + n] = M[(long long)(aBase + n) * CDIM + c];
        }
    }
    if (t < BN) y2s[buf * BN + t] = g_y2[aBase + t];
}

// ---- main fused kernel ----
__global__ __launch_bounds__(THREADS, 1)
void fused_main_kernel(const float* __restrict__ X,
                       const float* __restrict__ Ad,
                       const float* __restrict__ M) {
    extern __shared__ float sm[];
    float* As  = sm;                          // FD x SA
    float* Bs  = As + FD * SA;                // 2 x FD x SB
    float* Ps  = Bs + 2 * FD * SB;            // BM x SP
    float* Mst = Ps + BM * SP;                // 2 x CDIM x SMST
    float* y2s = Mst + 2 * CDIM * SMST;       // 2 x BN
    float* x2s = y2s + 2 * BN;                // BM

    int t = threadIdx.x;
    int tx = t & 15;
    int ty = t >> 4;
    int rowBase = blockIdx.x * BM;
    int sl = blockIdx.y;
    int aSliceBase = sl * APS;

    // Load A tile transposed: As[k][m]
    {
        int r = t >> 1;
        int kb = (t & 1) * 80;
        const float* src = X + (long long)(rowBase + r) * FD + kb;
        #pragma unroll
        for (int i = 0; i < 80; i += 4) {
            float4 v = *(const float4*)(src + i);
            As[(kb + i + 0) * SA + r] = v.x;
            As[(kb + i + 1) * SA + r] = v.y;
            As[(kb + i + 2) * SA + r] = v.z;
            As[(kb + i + 3) * SA + r] = v.w;
        }
    }
    __syncthreads();

    // x2 per row (conflict-free column read of As)
    if (t < BM) {
        float s = 0.f;
        for (int k = 0; k < FD; k++) {
            float v = As[k * SA + t];
            s = fmaf(v, v, s);
        }
        x2s[t] = s;
    }
    // Preload chunk 0
    loadChunk(0, aSliceBase, Ad, M, Bs, Mst, y2s, t);
    __syncthreads();

    // Persistent epilogue accumulators (packed even/odd-n lanes)
    unsigned long long acc2[6];
    #pragma unroll
    for (int i = 0; i < 6; i++) acc2[i] = 0ull;
    const unsigned long long ONE2 = dup2(1.0f);

    float x2r[8];
    #pragma unroll
    for (int i = 0; i < 8; i++) x2r[i] = x2s[ty * 8 + i];

    int row2 = t & 127;       // phase-2 row
    int cg = t >> 7;          // 0: c=0..4   1: c=5..9 + sum_w

    for (int ch = 0; ch < NCHUNK; ch++) {
        int buf = ch & 1;
        const float* Bb = Bs + buf * (FD * SB);

        // dot-product accumulators: 8 rows (4 packed pairs) x 4 cols
        unsigned long long dp[4][4];
        #pragma unroll
        for (int i = 0; i < 4; i++)
            #pragma unroll
            for (int j = 0; j < 4; j++) dp[i][j] = 0ull;

        #pragma unroll 8
        for (int k = 0; k < FD; k++) {
            const float* ak = As + k * SA + ty * 8;
            ulonglong2 A0 = *(const ulonglong2*)(ak);       // rows 0,1 | 2,3
            ulonglong2 A1 = *(const ulonglong2*)(ak + 4);   // rows 4,5 | 6,7
            float4 b = *(const float4*)(Bb + k * SB + tx * 4);
            unsigned long long b0 = dup2(b.x), b1 = dup2(b.y);
            unsigned long long b2 = dup2(b.z), b3 = dup2(b.w);
            fma2(dp[0][0], A0.x, b0); fma2(dp[0][1], A0.x, b1);
            fma2(dp[0][2], A0.x, b2); fma2(dp[0][3], A0.x, b3);
            fma2(dp[1][0], A0.y, b0); fma2(dp[1][1], A0.y, b1);
            fma2(dp[1][2], A0.y, b2); fma2(dp[1][3], A0.y, b3);
            fma2(dp[2][0], A1.x, b0); fma2(dp[2][1], A1.x, b1);
            fma2(dp[2][2], A1.x, b2); fma2(dp[2][3], A1.x, b3);
            fma2(dp[3][0], A1.y, b0); fma2(dp[3][1], A1.y, b1);
            fma2(dp[3][2], A1.y, b2); fma2(dp[3][3], A1.y, b3);
        }

        // Prefetch next chunk into the other buffer (overlaps with epilogue)
        if (ch + 1 < NCHUNK)
            loadChunk(1 - buf, aSliceBase + (ch + 1) * BN, Ad, M, Bs, Mst, y2s, t);

        // Phase 1: weights -> P tile
        {
            float4 y2v = *(const float4*)&y2s[buf * BN + tx * 4];
            float yy[4] = {y2v.x, y2v.y, y2v.z, y2v.w};
            #pragma unroll
            for (int ip = 0; ip < 4; ip++) {
                float w0[4], w1[4];
                float xa = x2r[2 * ip], xb = x2r[2 * ip + 1];
                #pragma unroll
                for (int j = 0; j < 4; j++) {
                    float2 d = unpk(dp[ip][j]);
                    float d2a = fmaf(-2.0f, d.x, xa + yy[j]);
                    float d2b = fmaf(-2.0f, d.y, xb + yy[j]);
                    w0[j] = __expf((SHIFT_C - sqrtf(fmaxf(d2a, 0.f))) * INVB);
                    w1[j] = __expf((SHIFT_C - sqrtf(fmaxf(d2b, 0.f))) * INVB);
                }
                float4* pr0 = (float4*)&Ps[(ty * 8 + 2 * ip) * SP + tx * 4];
                float4* pr1 = (float4*)&Ps[(ty * 8 + 2 * ip + 1) * SP + tx * 4];
                *pr0 = make_float4(w0[0], w0[1], w0[2], w0[3]);
                *pr1 = make_float4(w1[0], w1[1], w1[2], w1[3]);
            }
        }
        __syncthreads();

        // Phase 2: P[128x64] @ Mst[64 x 10(+1)] into persistent regs
        {
            const float* Pr = Ps + row2 * SP;
            const float* Mb = Mst + buf * (CDIM * SMST);
            int cbase = cg * 5;
            #pragma unroll
            for (int n4 = 0; n4 < 16; n4++) {
                ulonglong2 p = *(const ulonglong2*)(Pr + n4 * 4);
                #pragma unroll
                for (int cc = 0; cc < 5; cc++) {
                    const ulonglong2 m =
                        *(const ulonglong2*)(Mb + (cbase + cc) * SMST + n4 * 4);
                    fma2(acc2[cc], p.x, m.x);
                    fma2(acc2[cc], p.y, m.y);
                }
                if (cg) {  // sum of weights
                    fma2(acc2[5], p.x, ONE2);
                    fma2(acc2[5], p.y, ONE2);
                }
            }
        }
        __syncthreads();
    }

    // Write slice partials (each (row,c) slot written by exactly one thread)
    {
        int cbase = cg * 5;
        float* out = g_partial + ((long long)sl * NROWS + rowBase + row2) * 12;
        #pragma unroll
        for (int cc = 0; cc < 5; cc++) {
            float2 v = unpk(acc2[cc]);
            out[cbase + cc] = v.x + v.y;
        }
        if (cg) {
            float2 v = unpk(acc2[5]);
            out[10] = v.x + v.y;
        }
    }
}

// ---- finalize: sum slice partials, normalize ----
__global__ void finalize_kernel(float* __restrict__ out) {
    int idx = blockIdx.x * blockDim.x + threadIdx.x;  // n*CDIM + c
    if (idx >= NROWS * CDIM) return;
    int n = idx / CDIM;
    int c = idx - n * CDIM;
    float num = 0.f, den = 0.f;
    #pragma unroll
    for (int s = 0; s < SLICES; s++) {
        const float* p = g_partial + ((long long)s * NROWS + n) * 12;
        num += p[c];
        den += p[10];
    }
    out[idx] = num / den;
}

extern "C" void kernel_launch(void* const* d_in, const int* in_sizes, int n_in,
                              void* d_out, int out_size) {
    const float* X  = (const float*)d_in[0];   // inputs  [4096, 160]
    const float* Ad = (const float*)d_in[1];   // Address [32768, 160]
    const float* M  = (const float*)d_in[2];   // M       [32768, 10]
    float* out = (float*)d_out;                // [4096, 10]

    cudaFuncSetAttribute(fused_main_kernel,
                         cudaFuncAttributeMaxDynamicSharedMemorySize, SMEM_BYTES);

    prep_y2_kernel<<<AADDR / 8, 256>>>(Ad);
    fused_main_kernel<<<dim3(NROWS / BM, SLICES), THREADS, SMEM_BYTES>>>(X, Ad, M);
    finalize_kernel<<<(NROWS * CDIM + 255) / 256, 256>>>(out);
}

// round 3
// speedup vs baseline: 3.1154x; 3.1154x over previous
#include <cuda_runtime.h>
#include <cstdint>

#define NROWS 4096
#define AADDR 32768
#define FD    160
#define CDIM  10

#define BM 128
#define BN 64
#define SLICES 16
#define APS (AADDR / SLICES)     // 2048
#define NCH (APS / BN)           // 32
#define THREADS 256

// SMEM layout (bytes). Row stride 164 floats (656 B): 164 % 32 == 4 makes the
// mma fragment gather (addr = row*164 + k0 + tig) conflict-free across a warp.
#define SAK 164
#define A_BYTES   (BM * SAK * 4)          // 83968
#define B_BUF     (BN * SAK * 4)          // 41984
#define SM_A   0
#define SM_B   (SM_A + A_BYTES)           // 83968
#define SM_M   (SM_B + 2 * B_BUF)         // 167936 (2 x 2560)
#define SM_Y2  (SM_M + 2 * 2560)          // 173056 (2048 f32)
#define SM_X2  (SM_Y2 + 8192)             // 181248 (128 f32)
#define SMEM_TOTAL (SM_X2 + 512)          // 181760

#define KK 1.3115409462626940f   // log2(e)/1.1
#define CK 20.984655140203105f   // 16*log2(e)/1.1

__device__ float g_y2[AADDR];
__device__ float g_part[SLICES * 2 * NROWS * 12];

// ---------------- helpers ----------------
__device__ __forceinline__ uint32_t smem_u32(const void* p) {
    uint32_t a;
    asm("{ .reg .u64 t; cvta.to.shared.u64 t, %1; cvt.u32.u64 %0, t; }" : "=r"(a) : "l"(p));
    return a;
}
__device__ __forceinline__ float ex2f(float x) {
    float y; asm("ex2.approx.f32 %0, %1;" : "=f"(y) : "f"(x)); return y;
}
__device__ __forceinline__ float sqrt_ap(float x) {
    float y; asm("sqrt.approx.f32 %0, %1;" : "=f"(y) : "f"(x)); return y;
}
__device__ __forceinline__ unsigned long long dup2(float v) {
    unsigned long long r; asm("mov.b64 %0, {%1, %1};" : "=l"(r) : "f"(v)); return r;
}
__device__ __forceinline__ void fma2(unsigned long long& d, unsigned long long a, unsigned long long b) {
    asm("fma.rn.f32x2 %0, %1, %2, %0;" : "+l"(d) : "l"(a), "l"(b));
}
__device__ __forceinline__ float2 unpk(unsigned long long v) {
    float2 r; asm("mov.b64 {%0, %1}, %2;" : "=f"(r.x), "=f"(r.y) : "l"(v)); return r;
}
__device__ __forceinline__ void cp16(uint32_t dst, const void* src) {
    asm volatile("cp.async.cg.shared.global [%0], [%1], 16;" :: "r"(dst), "l"(src));
}
__device__ __forceinline__ void cp_commit() { asm volatile("cp.async.commit_group;" ::: "memory"); }
__device__ __forceinline__ void cp_wait1()  { asm volatile("cp.async.wait_group 1;" ::: "memory"); }
__device__ __forceinline__ void cp_wait0()  { asm volatile("cp.async.wait_group 0;" ::: "memory"); }

// m16n8k8 tf32 MMA (sm_80+, valid on plain sm_100 target)
__device__ __forceinline__ void mma8(float* c, const uint32_t* a, const uint32_t* b) {
    asm volatile("mma.sync.aligned.m16n8k8.row.col.f32.tf32.tf32.f32 "
                 "{%0,%1,%2,%3}, {%4,%5,%6,%7}, {%8,%9}, {%0,%1,%2,%3};"
                 : "+f"(c[0]), "+f"(c[1]), "+f"(c[2]), "+f"(c[3])
                 : "r"(a[0]), "r"(a[1]), "r"(a[2]), "r"(a[3]),
                   "r"(b[0]), "r"(b[1]));
}

// ---------------- prep: ||Address||^2 ----------------
__global__ void prep_y2_kernel(const float* __restrict__ Ad) {
    int row = blockIdx.x * 256 + threadIdx.x;
    const float4* p = (const float4*)(Ad + (size_t)row * FD);
    float s = 0.f;
    #pragma unroll
    for (int i = 0; i < FD / 4; i++) {
        float4 v = p[i];
        s = fmaf(v.x, v.x, s); s = fmaf(v.y, v.y, s);
        s = fmaf(v.z, v.z, s); s = fmaf(v.w, v.w, s);
    }
    g_y2[row] = s;
}

// ---------------- chunk loader (cp.async, no transpose) ----------------
__device__ __forceinline__ void issue_chunk(int c, int t, uint32_t sbase, int aSlice,
                                            const float* __restrict__ Ad,
                                            const float* __restrict__ M) {
    int buf = c & 1;
    int a0 = aSlice + c * BN;
    // B tile: 64 rows x 160 floats, row stride 656 B
    int r = t >> 2, q = t & 3;
    const char* src = (const char*)(Ad + (size_t)(a0 + r) * FD);
    uint32_t bdst = sbase + SM_B + buf * B_BUF + r * (SAK * 4);
    #pragma unroll
    for (int i = 0; i < 10; i++) {
        int j = q + 4 * i;                        // float4 index 0..39
        cp16(bdst + j * 16, src + j * 16);
    }
    if (t < (BN * CDIM) / 4)                      // M chunk: 2560 B contiguous
        cp16(sbase + SM_M + buf * 2560 + t * 16,
             (const char*)(M + (size_t)a0 * CDIM) + t * 16);
}

// ---------------- main fused kernel ----------------
__global__ __launch_bounds__(THREADS, 1)
void fused_mma_kernel(const float* __restrict__ X,
                      const float* __restrict__ Ad,
                      const float* __restrict__ M) {
    extern __shared__ __align__(1024) char sm[];
    uint32_t sbase = smem_u32(sm);
    const float* As = (const float*)(sm + SM_A);
    const float* y2s = (const float*)(sm + SM_Y2);

    int t = threadIdx.x;
    int wid = t >> 5, lane = t & 31;
    int g = lane >> 2, tig = lane & 3;
    int wm = wid & 3, wn = wid >> 2;
    int m0 = wm * 32, n0 = wn * 32;
    int rowBase = blockIdx.x * BM;
    int aSlice = blockIdx.y * APS;

    // stage A tile: 128 rows x 40 float4, row stride 656 B
    {
        int r = t >> 1;
        const char* src = (const char*)(X + (size_t)(rowBase + r) * FD);
        uint32_t adst = sbase + SM_A + r * (SAK * 4);
        #pragma unroll
        for (int i = 0; i < 20; i++) {
            int j = (t & 1) + 2 * i;
            cp16(adst + j * 16, src + j * 16);
        }
    }
    // stage y2 slice: 2048 floats = 512 float4
    cp16(sbase + SM_Y2 + t * 16, (const char*)(g_y2 + aSlice) + t * 16);
    cp16(sbase + SM_Y2 + (t + 256) * 16, (const char*)(g_y2 + aSlice) + (t + 256) * 16);
    // x2 per row (exact fp32, from global; L2-hot)
    if (t < BM) {
        const float4* p = (const float4*)(X + (size_t)(rowBase + t) * FD);
        float s = 0.f;
        #pragma unroll
        for (int i = 0; i < FD / 4; i++) {
            float4 v = p[i];
            s = fmaf(v.x, v.x, s); s = fmaf(v.y, v.y, s);
            s = fmaf(v.z, v.z, s); s = fmaf(v.w, v.w, s);
        }
        ((float*)(sm + SM_X2))[t] = s;
    }
    issue_chunk(0, t, sbase, aSlice, Ad, M);
    cp_commit();                                  // group: A + y2 + chunk0
    cp_wait0();
    __syncthreads();

    float x2r[4];                                 // rows m0+g+{0,8,16,24}
    #pragma unroll
    for (int i = 0; i < 4; i++) x2r[i] = ((const float*)(sm + SM_X2))[m0 + g + 8 * i];

    unsigned long long acc[4][5];
    float accw[4] = {0.f, 0.f, 0.f, 0.f};
    #pragma unroll
    for (int i = 0; i < 4; i++)
        #pragma unroll
        for (int p = 0; p < 5; p++) acc[i][p] = 0ull;

    for (int ch = 0; ch < NCH; ch++) {
        if (ch + 1 < NCH) {
            issue_chunk(ch + 1, t, sbase, aSlice, Ad, M);
            cp_commit();
            cp_wait1();
        } else {
            cp_wait0();
        }
        __syncthreads();

        const uint32_t* Bb = (const uint32_t*)(sm + SM_B + (ch & 1) * B_BUF);
        const uint32_t* Ab = (const uint32_t*)As;

        // D tile: 8 mma frags (2 mblocks x 4 nblocks), 4 regs each
        float c_[8][4];
        #pragma unroll
        for (int i = 0; i < 8; i++)
            #pragma unroll
            for (int j = 0; j < 4; j++) c_[i][j] = 0.f;

        #pragma unroll
        for (int ks = 0; ks < FD / 8; ks++) {
            int k0 = ks * 8;
            uint32_t a[2][4];
            #pragma unroll
            for (int mb = 0; mb < 2; mb++) {
                int rA = m0 + 16 * mb + g;
                a[mb][0] = Ab[rA * SAK + k0 + tig];
                a[mb][1] = Ab[(rA + 8) * SAK + k0 + tig];
                a[mb][2] = Ab[rA * SAK + k0 + tig + 4];
                a[mb][3] = Ab[(rA + 8) * SAK + k0 + tig + 4];
            }
            #pragma unroll
            for (int nb = 0; nb < 4; nb++) {
                uint32_t b[2];
                int rB = n0 + 8 * nb + g;
                b[0] = Bb[rB * SAK + k0 + tig];
                b[1] = Bb[rB * SAK + k0 + tig + 4];
                mma8(c_[0 * 4 + nb], a[0], b);
                mma8(c_[1 * 4 + nb], a[1], b);
            }
        }

        // epilogue: w = exp2(CK - KK*dist), acc += w * M[n][:]
        const float2* Ms2 = (const float2*)(sm + SM_M + (ch & 1) * 2560);
        #pragma unroll
        for (int nb = 0; nb < 4; nb++) {
            #pragma unroll
            for (int c2 = 0; c2 < 2; c2++) {
                int nl = n0 + 8 * nb + 2 * tig + c2;
                float y2v = y2s[ch * BN + nl];
                unsigned long long m01, m23, m45, m67, m89;
                {
                    const float2* mr = Ms2 + nl * 5;
                    float2 v0 = mr[0], v1 = mr[1], v2 = mr[2], v3 = mr[3], v4 = mr[4];
                    asm("mov.b64 %0, {%1, %2};" : "=l"(m01) : "f"(v0.x), "f"(v0.y));
                    asm("mov.b64 %0, {%1, %2};" : "=l"(m23) : "f"(v1.x), "f"(v1.y));
                    asm("mov.b64 %0, {%1, %2};" : "=l"(m45) : "f"(v2.x), "f"(v2.y));
                    asm("mov.b64 %0, {%1, %2};" : "=l"(m67) : "f"(v3.x), "f"(v3.y));
                    asm("mov.b64 %0, {%1, %2};" : "=l"(m89) : "f"(v4.x), "f"(v4.y));
                }
                #pragma unroll
                for (int mb = 0; mb < 2; mb++) {
                    #pragma unroll
                    for (int h = 0; h < 2; h++) {
                        int ri = 2 * mb + h;
                        float d = c_[mb * 4 + nb][h * 2 + c2];
                        float q = fmaxf(fmaf(-2.f, d, x2r[ri] + y2v), 1e-12f);
                        float w = ex2f(fmaf(sqrt_ap(q), -KK, CK));
                        accw[ri] += w;
                        unsigned long long W = dup2(w);
                        fma2(acc[ri][0], W, m01);
                        fma2(acc[ri][1], W, m23);
                        fma2(acc[ri][2], W, m45);
                        fma2(acc[ri][3], W, m67);
                        fma2(acc[ri][4], W, m89);
                    }
                }
            }
        }
        __syncthreads();
    }

    // reduce across tig (4 lanes share the same m rows), then write partials
    {
        #pragma unroll
        for (int ri = 0; ri < 4; ri++) {
            float v[11];
            #pragma unroll
            for (int p = 0; p < 5; p++) {
                float2 u = unpk(acc[ri][p]);
                v[2 * p] = u.x; v[2 * p + 1] = u.y;
            }
            v[10] = accw[ri];
            #pragma unroll
            for (int j = 0; j < 11; j++) {
                v[j] += __shfl_xor_sync(0xffffffffu, v[j], 1);
                v[j] += __shfl_xor_sync(0xffffffffu, v[j], 2);
            }
            if (tig == 0) {
                int mb = ri >> 1, h = ri & 1;
                int grow = rowBase + m0 + 16 * mb + 8 * h + g;
                float* out = g_part + ((size_t)(blockIdx.y * 2 + wn) * NROWS + grow) * 12;
                #pragma unroll
                for (int j = 0; j < 11; j++) out[j] = v[j];
            }
        }
    }
}

// ---------------- finalize ----------------
__global__ void finalize_kernel(float* __restrict__ out) {
    int idx = blockIdx.x * blockDim.x + threadIdx.x;
    if (idx >= NROWS * CDIM) return;
    int n = idx / CDIM;
    int c = idx - n * CDIM;
    float num = 0.f, den = 0.f;
    #pragma unroll
    for (int s = 0; s < SLICES * 2; s++) {
        const float* p = g_part + ((size_t)s * NROWS + n) * 12;
        num += p[c];
        den += p[10];
    }
    out[idx] = num / den;
}

extern "C" void kernel_launch(void* const* d_in, const int* in_sizes, int n_in,
                              void* d_out, int out_size) {
    const float* X  = (const float*)d_in[0];   // inputs  [4096, 160]
    const float* Ad = (const float*)d_in[1];   // Address [32768, 160]
    const float* M  = (const float*)d_in[2];   // M       [32768, 10]
    float* out = (float*)d_out;                // [4096, 10]

    cudaFuncSetAttribute(fused_mma_kernel,
                         cudaFuncAttributeMaxDynamicSharedMemorySize, SMEM_TOTAL);

    prep_y2_kernel<<<AADDR / 256, 256>>>(Ad);
    fused_mma_kernel<<<dim3(NROWS / BM, SLICES), THREADS, SMEM_TOTAL>>>(X, Ad, M);
    finalize_kernel<<<(NROWS * CDIM + 255) / 256, 256>>>(out);
}

// round 4
// speedup vs baseline: 3.1387x; 1.0075x over previous
#include <cuda_runtime.h>
#include <cstdint>

#define NROWS 4096
#define AADDR 32768
#define FD    160
#define CDIM  10

#define BM 128
#define BN 64
#define SLICES 16
#define APS (AADDR / SLICES)     // 2048
#define NCH (APS / BN)           // 32
#define THREADS 256

// Row stride 164 floats (656 B): 164 % 32 == 4 -> every 8-row ldmatrix phase
// covers all 32 banks (conflict-free).
#define SAK 164
#define A_BYTES   (BM * SAK * 4)          // 83968
#define B_BUF     (BN * SAK * 4)          // 41984
#define SM_A   0
#define SM_B   (SM_A + A_BYTES)           // 83968
#define SM_M   (SM_B + 2 * B_BUF)         // 167936 (2 x 2560)
#define SM_Y2  (SM_M + 2 * 2560)          // 173056 (2048 f32)
#define SM_X2  (SM_Y2 + 8192)             // 181248 (128 f32)
#define SMEM_TOTAL (SM_X2 + 512)          // 181760

#define KK 1.3115409462626940f   // log2(e)/1.1
#define CK 20.984655140203105f   // 16*log2(e)/1.1

__device__ float g_y2[AADDR];
__device__ float g_part[SLICES * 2 * NROWS * 12];

// ---------------- helpers ----------------
__device__ __forceinline__ uint32_t smem_u32(const void* p) {
    uint32_t a;
    asm("{ .reg .u64 t; cvta.to.shared.u64 t, %1; cvt.u32.u64 %0, t; }" : "=r"(a) : "l"(p));
    return a;
}
__device__ __forceinline__ float ex2f(float x) {
    float y; asm("ex2.approx.f32 %0, %1;" : "=f"(y) : "f"(x)); return y;
}
__device__ __forceinline__ float sqrt_ap(float x) {
    float y; asm("sqrt.approx.f32 %0, %1;" : "=f"(y) : "f"(x)); return y;
}
__device__ __forceinline__ unsigned long long dup2(float v) {
    unsigned long long r; asm("mov.b64 %0, {%1, %1};" : "=l"(r) : "f"(v)); return r;
}
__device__ __forceinline__ void fma2(unsigned long long& d, unsigned long long a, unsigned long long b) {
    asm("fma.rn.f32x2 %0, %1, %2, %0;" : "+l"(d) : "l"(a), "l"(b));
}
__device__ __forceinline__ float2 unpk(unsigned long long v) {
    float2 r; asm("mov.b64 {%0, %1}, %2;" : "=f"(r.x), "=f"(r.y) : "l"(v)); return r;
}
__device__ __forceinline__ void cp16(uint32_t dst, const void* src) {
    asm volatile("cp.async.cg.shared.global [%0], [%1], 16;" :: "r"(dst), "l"(src));
}
__device__ __forceinline__ void cp_commit() { asm volatile("cp.async.commit_group;" ::: "memory"); }
__device__ __forceinline__ void cp_wait1()  { asm volatile("cp.async.wait_group 1;" ::: "memory"); }
__device__ __forceinline__ void cp_wait0()  { asm volatile("cp.async.wait_group 0;" ::: "memory"); }

// ldmatrix x4: lane l -> tile l>>3, row l&7. Returns (row g=lane>>2, b32col tig=lane&3)
// of each 8x4-b32 tile: exactly the tf32 m16n8k8 fragment layout.
__device__ __forceinline__ void ldsm4(uint32_t* r, uint32_t addr) {
    asm volatile("ldmatrix.sync.aligned.m8n8.x4.shared.b16 {%0,%1,%2,%3}, [%4];"
                 : "=r"(r[0]), "=r"(r[1]), "=r"(r[2]), "=r"(r[3]) : "r"(addr));
}

// m16n8k8 tf32 MMA (sm_80+, valid on plain sm_100 target)
__device__ __forceinline__ void mma8(float* c, const uint32_t* a, const uint32_t* b) {
    asm volatile("mma.sync.aligned.m16n8k8.row.col.f32.tf32.tf32.f32 "
                 "{%0,%1,%2,%3}, {%4,%5,%6,%7}, {%8,%9}, {%0,%1,%2,%3};"
                 : "+f"(c[0]), "+f"(c[1]), "+f"(c[2]), "+f"(c[3])
                 : "r"(a[0]), "r"(a[1]), "r"(a[2]), "r"(a[3]),
                   "r"(b[0]), "r"(b[1]));
}

// ---------------- prep: ||Address||^2 (warp per row, coalesced) ----------------
__global__ void prep_y2_kernel(const float* __restrict__ Ad) {
    int row = (blockIdx.x * 256 + threadIdx.x) >> 5;
    int lane = threadIdx.x & 31;
    const float4* p = (const float4*)(Ad + (size_t)row * FD);
    float4 v = p[lane];
    float s = v.x * v.x + v.y * v.y + v.z * v.z + v.w * v.w;
    if (lane < 8) {
        float4 u = p[32 + lane];
        s += u.x * u.x + u.y * u.y + u.z * u.z + u.w * u.w;
    }
    #pragma unroll
    for (int o = 16; o; o >>= 1) s += __shfl_xor_sync(0xffffffffu, s, o);
    if (lane == 0) g_y2[row] = s;
}

// ---------------- chunk loader (cp.async, no transpose) ----------------
__device__ __forceinline__ void issue_chunk(int c, int t, uint32_t sbase, int aSlice,
                                            const float* __restrict__ Ad,
                                            const float* __restrict__ M) {
    int buf = c & 1;
    int a0 = aSlice + c * BN;
    int r = t >> 2, q = t & 3;
    const char* src = (const char*)(Ad + (size_t)(a0 + r) * FD);
    uint32_t bdst = sbase + SM_B + buf * B_BUF + r * (SAK * 4);
    #pragma unroll
    for (int i = 0; i < 10; i++) {
        int j = q + 4 * i;
        cp16(bdst + j * 16, src + j * 16);
    }
    if (t < (BN * CDIM) / 4)
        cp16(sbase + SM_M + buf * 2560 + t * 16,
             (const char*)(M + (size_t)a0 * CDIM) + t * 16);
}

// ---------------- main fused kernel ----------------
__global__ __launch_bounds__(THREADS, 1)
void fused_mma_kernel(const float* __restrict__ X,
                      const float* __restrict__ Ad,
                      const float* __restrict__ M) {
    extern __shared__ __align__(1024) char sm[];
    uint32_t sbase = smem_u32(sm);
    const float* y2s = (const float*)(sm + SM_Y2);

    int t = threadIdx.x;
    int wid = t >> 5, lane = t & 31;
    int g = lane >> 2, tig = lane & 3;
    int wm = wid & 3, wn = wid >> 2;
    int m0 = wm * 32, n0 = wn * 32;
    int rowBase = blockIdx.x * BM;
    int aSlice = blockIdx.y * APS;

    // stage A tile
    {
        int r = t >> 1;
        const char* src = (const char*)(X + (size_t)(rowBase + r) * FD);
        uint32_t adst = sbase + SM_A + r * (SAK * 4);
        #pragma unroll
        for (int i = 0; i < 20; i++) {
            int j = (t & 1) + 2 * i;
            cp16(adst + j * 16, src + j * 16);
        }
    }
    // stage y2 slice
    cp16(sbase + SM_Y2 + t * 16, (const char*)(g_y2 + aSlice) + t * 16);
    cp16(sbase + SM_Y2 + (t + 256) * 16, (const char*)(g_y2 + aSlice) + (t + 256) * 16);
    // x2 per row (exact fp32)
    if (t < BM) {
        const float4* p = (const float4*)(X + (size_t)(rowBase + t) * FD);
        float s = 0.f;
        #pragma unroll
        for (int i = 0; i < FD / 4; i++) {
            float4 v = p[i];
            s = fmaf(v.x, v.x, s); s = fmaf(v.y, v.y, s);
            s = fmaf(v.z, v.z, s); s = fmaf(v.w, v.w, s);
        }
        ((float*)(sm + SM_X2))[t] = s;
    }
    issue_chunk(0, t, sbase, aSlice, Ad, M);
    cp_commit();
    cp_wait0();
    __syncthreads();

    float x2r[4];
    #pragma unroll
    for (int i = 0; i < 4; i++) x2r[i] = ((const float*)(sm + SM_X2))[m0 + g + 8 * i];

    // ldmatrix per-lane base addresses
    int tr = lane & 7, tt = lane >> 3;
    // A: tile0 rows+0 @k0 | tile1 rows+8 @k0 | tile2 rows+0 @k0+4 | tile3 rows+8 @k0+4
    uint32_t aBase0 = sbase + SM_A +
        (((m0 + (tt & 1) * 8 + tr) * SAK) + (tt >> 1) * 4) * 4;
    uint32_t aBase1 = aBase0 + 16 * SAK * 4;
    // B ldsm j: tile0 nb(2j) @k0 | tile1 nb(2j) @k0+4 | tile2 nb(2j+1) @k0 | tile3 nb(2j+1) @k0+4
    uint32_t bOff0 = ((n0 + 8 * (tt >> 1) + tr) * SAK + (tt & 1) * 4) * 4;
    uint32_t bOff1 = bOff0 + 16 * SAK * 4;

    unsigned long long acc[4][5];
    float accw[4] = {0.f, 0.f, 0.f, 0.f};
    #pragma unroll
    for (int i = 0; i < 4; i++)
        #pragma unroll
        for (int p = 0; p < 5; p++) acc[i][p] = 0ull;

    for (int ch = 0; ch < NCH; ch++) {
        if (ch + 1 < NCH) {
            issue_chunk(ch + 1, t, sbase, aSlice, Ad, M);
            cp_commit();
            cp_wait1();
        } else {
            cp_wait0();
        }
        __syncthreads();

        uint32_t bBase = sbase + SM_B + (ch & 1) * B_BUF;

        float c_[8][4];
        #pragma unroll
        for (int i = 0; i < 8; i++)
            #pragma unroll
            for (int j = 0; j < 4; j++) c_[i][j] = 0.f;

        #pragma unroll
        for (int ks = 0; ks < FD / 8; ks++) {
            uint32_t a0[4], a1[4], b0[4], b1[4];
            ldsm4(a0, aBase0 + ks * 32);
            ldsm4(a1, aBase1 + ks * 32);
            ldsm4(b0, bBase + bOff0 + ks * 32);
            ldsm4(b1, bBase + bOff1 + ks * 32);
            mma8(c_[0], a0, b0);     mma8(c_[1], a0, b0 + 2);
            mma8(c_[2], a0, b1);     mma8(c_[3], a0, b1 + 2);
            mma8(c_[4], a1, b0);     mma8(c_[5], a1, b0 + 2);
            mma8(c_[6], a1, b1);     mma8(c_[7], a1, b1 + 2);
        }

        // epilogue: w = exp2(CK - KK*dist), acc += w * M[n][:]
        const float2* Ms2 = (const float2*)(sm + SM_M + (ch & 1) * 2560);
        #pragma unroll
        for (int nb = 0; nb < 4; nb++) {
            #pragma unroll
            for (int c2 = 0; c2 < 2; c2++) {
                int nl = n0 + 8 * nb + 2 * tig + c2;
                float y2v = y2s[ch * BN + nl];
                unsigned long long m01, m23, m45, m67, m89;
                {
                    const float2* mr = Ms2 + nl * 5;
                    float2 v0 = mr[0], v1 = mr[1], v2 = mr[2], v3 = mr[3], v4 = mr[4];
                    asm("mov.b64 %0, {%1, %2};" : "=l"(m01) : "f"(v0.x), "f"(v0.y));
                    asm("mov.b64 %0, {%1, %2};" : "=l"(m23) : "f"(v1.x), "f"(v1.y));
                    asm("mov.b64 %0, {%1, %2};" : "=l"(m45) : "f"(v2.x), "f"(v2.y));
                    asm("mov.b64 %0, {%1, %2};" : "=l"(m67) : "f"(v3.x), "f"(v3.y));
                    asm("mov.b64 %0, {%1, %2};" : "=l"(m89) : "f"(v4.x), "f"(v4.y));
                }
                #pragma unroll
                for (int mb = 0; mb < 2; mb++) {
                    #pragma unroll
                    for (int h = 0; h < 2; h++) {
                        int ri = 2 * mb + h;
                        float d = c_[mb * 4 + nb][h * 2 + c2];
                        float q = fmaxf(fmaf(-2.f, d, x2r[ri] + y2v), 1e-12f);
                        float w = ex2f(fmaf(sqrt_ap(q), -KK, CK));
                        accw[ri] += w;
                        unsigned long long W = dup2(w);
                        fma2(acc[ri][0], W, m01);
                        fma2(acc[ri][1], W, m23);
                        fma2(acc[ri][2], W, m45);
                        fma2(acc[ri][3], W, m67);
                        fma2(acc[ri][4], W, m89);
                    }
                }
            }
        }
        __syncthreads();
    }

    // reduce across tig, write partials
    {
        #pragma unroll
        for (int ri = 0; ri < 4; ri++) {
            float v[11];
            #pragma unroll
            for (int p = 0; p < 5; p++) {
                float2 u = unpk(acc[ri][p]);
                v[2 * p] = u.x; v[2 * p + 1] = u.y;
            }
            v[10] = accw[ri];
            #pragma unroll
            for (int j = 0; j < 11; j++) {
                v[j] += __shfl_xor_sync(0xffffffffu, v[j], 1);
                v[j] += __shfl_xor_sync(0xffffffffu, v[j], 2);
            }
            if (tig == 0) {
                int mb = ri >> 1, h = ri & 1;
                int grow = rowBase + m0 + 16 * mb + 8 * h + g;
                float* out = g_part + ((size_t)(blockIdx.y * 2 + wn) * NROWS + grow) * 12;
                #pragma unroll
                for (int j = 0; j < 11; j++) out[j] = v[j];
            }
        }
    }
}

// ---------------- finalize ----------------
__global__ void finalize_kernel(float* __restrict__ out) {
    int idx = blockIdx.x * blockDim.x + threadIdx.x;
    if (idx >= NROWS * CDIM) return;
    int n = idx / CDIM;
    int c = idx - n * CDIM;
    float num = 0.f, den = 0.f;
    #pragma unroll
    for (int s = 0; s < SLICES * 2; s++) {
        const float* p = g_part + ((size_t)s * NROWS + n) * 12;
        num += p[c];
        den += p[10];
    }
    out[idx] = num / den;
}

extern "C" void kernel_launch(void* const* d_in, const int* in_sizes, int n_in,
                              void* d_out, int out_size) {
    const float* X  = (const float*)d_in[0];   // inputs  [4096, 160]
    const float* Ad = (const float*)d_in[1];   // Address [32768, 160]
    const float* M  = (const float*)d_in[2];   // M       [32768, 10]
    float* out = (float*)d_out;                // [4096, 10]

    cudaFuncSetAttribute(fused_mma_kernel,
                         cudaFuncAttributeMaxDynamicSharedMemorySize, SMEM_TOTAL);

    prep_y2_kernel<<<AADDR / 8, 256>>>(Ad);
    fused_mma_kernel<<<dim3(NROWS / BM, SLICES), THREADS, SMEM_TOTAL>>>(X, Ad, M);
    finalize_kernel<<<(NROWS * CDIM + 255) / 256, 256>>>(out);
}